// round 1
// baseline (speedup 1.0000x reference)
#include <cuda_runtime.h>
#include <cstdint>

// ModernNet fused inference, f32x2-packed (2 samples per lane).
// Layout: 8 sample-pairs (16 samples) per 128-thread block.
// Phases: load -> conv1(96 thr) -> conv2(96 thr) -> warp-cooperative FC.

typedef unsigned long long u64;

#define NEG1U 0xBF800000BF800000ull   // (-1.0f, -1.0f)

// packed fp32x2 fma: d = a*b + c (Blackwell FFMA2 path, PTX-only)
__device__ __forceinline__ u64 fma2(u64 a, u64 b, u64 c) {
    u64 d;
    asm("fma.rn.f32x2 %0, %1, %2, %3;" : "=l"(d) : "l"(a), "l"(b), "l"(c));
    return d;
}
__device__ __forceinline__ u64 bcast(float w) {
    u64 d; unsigned int u = __float_as_uint(w);
    asm("mov.b64 %0, {%1, %1};" : "=l"(d) : "r"(u));
    return d;
}
__device__ __forceinline__ u64 pack2(float lo, float hi) {
    u64 d;
    asm("mov.b64 %0, {%1, %2};" : "=l"(d)
        : "r"(__float_as_uint(lo)), "r"(__float_as_uint(hi)));
    return d;
}
__device__ __forceinline__ float2 unpack2(u64 a) {
    unsigned int l, h;
    asm("mov.b64 {%0, %1}, %2;" : "=r"(l), "=r"(h) : "l"(a));
    return make_float2(__uint_as_float(l), __uint_as_float(h));
}
__device__ __forceinline__ u64 relu2(u64 a) {
    float2 f = unpack2(a);
    return pack2(fmaxf(f.x, 0.f), fmaxf(f.y, 0.f));
}

// ---- shared memory layout (bytes) ----
// sW1 300f @0 | sW2 2400f @1200 | sW3 5760f @10800 | (weights end 33840)
// xsU 8*405 u64 @33840 (padded x, stride 405 to dodge bank conflicts)
// a1U 8*12*65 u64 @59760 (plane stride 65)
// overlays on xs region after conv1:
//   a2U 8*205 u64 @33840 (pair stride 205, channel stride 17)
//   hsU 8*30 u64 @46960
static const int SMEM_BYTES = 59760 + 8 * 12 * 65 * 8;   // 109680

__global__ __launch_bounds__(128, 2)
void modnet_kernel(const float* __restrict__ gx,
                   const float* __restrict__ gW1, const float* __restrict__ gB1,
                   const float* __restrict__ gW2, const float* __restrict__ gB2,
                   const float* __restrict__ gW3, const float* __restrict__ gB3,
                   const float* __restrict__ gWo, const float* __restrict__ gBo,
                   float* __restrict__ gout, int totalPairs)
{
    extern __shared__ __align__(16) unsigned char sm[];
    float* sW1 = (float*)sm;             // 300
    float* sW2 = sW1 + 300;              // 2400
    float* sW3 = sW2 + 2400;             // 5760
    u64* xsU = (u64*)(sm + 33840);       // 8 * 405
    u64* a1U = (u64*)(sm + 59760);       // 8 * 12 * 65
    u64* a2U = (u64*)(sm + 33840);       // overlay, 8 * 205
    u64* hsU = (u64*)(sm + 46960);       // overlay, 8 * 30

    const int tid = threadIdx.x;
    const int pairbase = blockIdx.x * 8;

    // ---- stage weights + init padded-x to -1 ----
    for (int i = tid; i < 300;  i += 128) sW1[i] = gW1[i];
    for (int i = tid; i < 2400; i += 128) sW2[i] = gW2[i];
    for (int i = tid; i < 5760; i += 128) sW3[i] = gW3[i];
    for (int i = tid; i < 8 * 405; i += 128) xsU[i] = NEG1U;
    __syncthreads();

    // ---- load x interior: 16 samples * 256 pixels, coalesced ----
    {
        const float* xsrc = gx + (size_t)pairbase * 512;
        int avail = (totalPairs - pairbase) * 2;            // samples available
        int nval = (avail > 16 ? 16 : avail) * 256;
        for (int idx = tid; idx < 4096; idx += 128) {
            if (idx < nval) {
                float v = xsrc[idx];
                int sl = idx >> 8, pix = idx & 255;
                int p = sl >> 1, half = sl & 1;
                int yy = pix >> 4, xx = pix & 15;
                ((float*)(xsU + p * 405 + (yy + 2) * 20 + (xx + 2)))[half] = v;
            }
        }
    }
    __syncthreads();

    // ---- conv1: 1 -> 12 ch, 5x5 stride 2 on padded 20x20 -> 8x8, +bias, relu
    if (tid < 96) {
        int p = tid / 12, c = tid - 12 * p;
        const u64* xp = xsU + p * 405;
        u64 wp[25];
        #pragma unroll
        for (int i = 0; i < 25; i++) wp[i] = bcast(sW1[c * 25 + i]);
        const float* bias = gB1 + c * 64;
        u64* a1c = a1U + (p * 12 + c) * 65;
        #pragma unroll 1
        for (int y = 0; y < 8; y++) {
            u64 acc[8];
            #pragma unroll
            for (int xo = 0; xo < 8; xo++) acc[xo] = bcast(bias[y * 8 + xo]);
            #pragma unroll
            for (int ky = 0; ky < 5; ky++) {
                const u64* row = xp + (2 * y + ky) * 20;
                u64 r[19];
                #pragma unroll
                for (int i = 0; i < 19; i++) r[i] = row[i];
                #pragma unroll
                for (int kx = 0; kx < 5; kx++) {
                    u64 wv = wp[ky * 5 + kx];
                    #pragma unroll
                    for (int xo = 0; xo < 8; xo++)
                        acc[xo] = fma2(r[2 * xo + kx], wv, acc[xo]);
                }
            }
            #pragma unroll
            for (int xo = 0; xo < 8; xo++) a1c[y * 8 + xo] = relu2(acc[xo]);
        }
    }
    __syncthreads();

    // ---- conv2: grouped (8 in-ch each), 5x5 stride 2 on padded 12x12 -> 4x4
    if (tid < 96) {
        int p = tid / 12, oc = tid - 12 * p;
        int g = oc >> 2;
        u64 acc[16];
        const float* b2 = gB2 + oc * 16;
        #pragma unroll
        for (int i = 0; i < 16; i++) acc[i] = bcast(b2[i]);
        const float* w2 = sW2 + oc * 200;
        #pragma unroll 1
        for (int ic8 = 0; ic8 < 8; ic8++) {
            int cin = (g == 0) ? ic8
                    : (g == 1) ? (ic8 + 4)
                    : ((ic8 < 4) ? ic8 : ic8 + 4);
            u64 wv[25];
            #pragma unroll
            for (int i = 0; i < 25; i++) wv[i] = bcast(w2[ic8 * 25 + i]);
            const u64* plane = a1U + (p * 12 + cin) * 65;
            #pragma unroll
            for (int iy = -2; iy <= 8; iy++) {
                u64 r[11];
                #pragma unroll
                for (int j = 0; j < 11; j++) {
                    int ix = j - 2;
                    r[j] = (iy >= 0 && iy < 8 && ix >= 0 && ix < 8)
                           ? plane[iy * 8 + ix] : NEG1U;
                }
                #pragma unroll
                for (int oy = 0; oy < 4; oy++) {
                    int ky = iy + 2 - 2 * oy;
                    if (ky >= 0 && ky < 5) {
                        #pragma unroll
                        for (int kx = 0; kx < 5; kx++) {
                            u64 wvv = wv[ky * 5 + kx];
                            #pragma unroll
                            for (int ox = 0; ox < 4; ox++)
                                acc[oy * 4 + ox] =
                                    fma2(r[2 * ox + kx], wvv, acc[oy * 4 + ox]);
                        }
                    }
                }
            }
        }
        // store a2 with channel stride 17 (bank-conflict-free), relu
        u64* a2p = a2U + p * 205 + oc * 17;
        #pragma unroll
        for (int i = 0; i < 16; i++) a2p[i] = relu2(acc[i]);
    }
    __syncthreads();

    // ---- FC: warp-cooperative. Each warp owns 2 pairs; lane = output neuron.
    {
        int wid = tid >> 5, lane = tid & 31;
        int jl = lane < 30 ? lane : 29;
        u64 bj = bcast(gB3[jl]);
        #pragma unroll 1
        for (int pp = 0; pp < 2; pp++) {
            int p = wid * 2 + pp;
            const u64* a2p = a2U + p * 205;
            u64 acc = bj;
            #pragma unroll 4
            for (int k = 0; k < 192; k++) {
                // a2 physical index: k + k/16 (channel-stride-17 layout)
                u64 av = a2p[k + (k >> 4)];        // smem broadcast
                acc = fma2(av, bcast(sW3[k * 30 + jl]), acc);
            }
            acc = relu2(acc);
            if (lane < 30) hsU[p * 30 + lane] = acc;
            __syncwarp();
            if (lane < 10) {
                u64 o = bcast(gBo[lane]);
                #pragma unroll
                for (int k = 0; k < 30; k++)
                    o = fma2(hsU[p * 30 + k], bcast(gWo[k * 10 + lane]), o);
                int gp = pairbase + p;
                if (gp < totalPairs) {
                    float2 f = unpack2(o);
                    gout[(size_t)(2 * gp) * 10 + lane]     = f.x;
                    gout[(size_t)(2 * gp + 1) * 10 + lane] = f.y;
                }
            }
            __syncwarp();
        }
    }
}

extern "C" void kernel_launch(void* const* d_in, const int* in_sizes, int n_in,
                              void* d_out, int out_size)
{
    const float* x  = (const float*)d_in[0];
    const float* w1 = (const float*)d_in[1];
    const float* b1 = (const float*)d_in[2];
    const float* w2 = (const float*)d_in[3];
    const float* b2 = (const float*)d_in[4];
    const float* w3 = (const float*)d_in[5];
    const float* b3 = (const float*)d_in[6];
    const float* wo = (const float*)d_in[7];
    const float* bo = (const float*)d_in[8];
    float* out = (float*)d_out;

    int Bn = in_sizes[0] / 256;         // number of samples
    int pairs = Bn / 2;
    int blocks = (pairs + 7) / 8;

    cudaFuncSetAttribute(modnet_kernel,
                         cudaFuncAttributeMaxDynamicSharedMemorySize, SMEM_BYTES);
    modnet_kernel<<<blocks, 128, SMEM_BYTES>>>(x, w1, b1, w2, b2, w3, b3,
                                               wo, bo, out, pairs);
}

// round 2
// speedup vs baseline: 1.1752x; 1.1752x over previous
#include <cuda_runtime.h>
#include <cstdint>

// ModernNet fused inference, f32x2-packed (2 samples per lane), v2.
// 8 sample-pairs per 128-thread block, 3 CTAs/SM (77.3KB smem).
// Conv phases: lanes 0-23 of each warp active (2 pairs per warp).

typedef unsigned long long u64;

#define NEG1U 0xBF800000BF800000ull   // (-1.0f, -1.0f)

__device__ __forceinline__ u64 fma2(u64 a, u64 b, u64 c) {
    u64 d;
    asm("fma.rn.f32x2 %0, %1, %2, %3;" : "=l"(d) : "l"(a), "l"(b), "l"(c));
    return d;
}
__device__ __forceinline__ u64 add2(u64 a, u64 b) {
    u64 d;
    asm("add.rn.f32x2 %0, %1, %2;" : "=l"(d) : "l"(a), "l"(b));
    return d;
}
__device__ __forceinline__ u64 bcast(float w) {
    u64 d; unsigned int u = __float_as_uint(w);
    asm("mov.b64 %0, {%1, %1};" : "=l"(d) : "r"(u));
    return d;
}
__device__ __forceinline__ u64 pack2(float lo, float hi) {
    u64 d;
    asm("mov.b64 %0, {%1, %2};" : "=l"(d)
        : "r"(__float_as_uint(lo)), "r"(__float_as_uint(hi)));
    return d;
}
__device__ __forceinline__ float2 unpack2(u64 a) {
    unsigned int l, h;
    asm("mov.b64 {%0, %1}, %2;" : "=r"(l), "=r"(h) : "l"(a));
    return make_float2(__uint_as_float(l), __uint_as_float(h));
}
__device__ __forceinline__ u64 relu2(u64 a) {
    float2 f = unpack2(a);
    return pack2(fmaxf(f.x, 0.f), fmaxf(f.y, 0.f));
}

// ---- shared memory layout (bytes) ----
// sW1 @0     : 300 f                       (1200 B)
// sW2 @1200  : 12 oc * stride 202 f        (9696 B)   end 10896 -> align 10912
// xsU @10912 : 8 pairs * stride 257 u64    (16448 B)  end 27360
// a1U @27360 : 8 pairs * 12 ch * 65 u64    (49920 B)  end 77280
// overlays on xs after conv1:
//   a2U @10912 : 8 * 205 u64 (pair stride 205, ch stride 17)
//   hsU @24032 : 8 * 30 u64
static const int XS_OFF = 10912;
static const int A1_OFF = XS_OFF + 2056 * 8;           // 27360
static const int SMEM_BYTES = A1_OFF + 6240 * 8;       // 77280
static const int HS_OFF = XS_OFF + 1640 * 8;           // 24032

// conv1: accumulate one valid input row (16 u64) against 5 weights.
// Compile-time x-edge handling: ix outside [0,16) contributes -1.
__device__ __forceinline__ void c1_row(const u64* __restrict__ row,
                                       const u64* wk, u64* acc, u64 neg1) {
    u64 rw[16];
#pragma unroll
    for (int i = 0; i < 16; i++) rw[i] = row[i];
#pragma unroll
    for (int kx = 0; kx < 5; kx++) {
        u64 wv = wk[kx];
#pragma unroll
        for (int xo = 0; xo < 8; xo++) {
            int ix = 2 * xo + kx - 2;
            u64 v = (ix >= 0 && ix < 16) ? rw[ix] : neg1;
            acc[xo] = fma2(v, wv, acc[xo]);
        }
    }
}

__global__ __launch_bounds__(128, 3)
void modnet_kernel(const float* __restrict__ gx,
                   const float* __restrict__ gW1, const float* __restrict__ gB1,
                   const float* __restrict__ gW2, const float* __restrict__ gB2,
                   const float* __restrict__ gW3, const float* __restrict__ gB3,
                   const float* __restrict__ gWo, const float* __restrict__ gBo,
                   float* __restrict__ gout, int totalPairs)
{
    extern __shared__ __align__(16) unsigned char sm[];
    float* sW1 = (float*)sm;                  // 300
    float* sW2 = (float*)(sm + 1200);         // 12 * 202
    u64* xsU = (u64*)(sm + XS_OFF);           // 8 * 257
    u64* a1U = (u64*)(sm + A1_OFF);           // 8 * 12 * 65
    u64* a2U = (u64*)(sm + XS_OFF);           // overlay
    u64* hsU = (u64*)(sm + HS_OFF);           // overlay

    const int tid = threadIdx.x;
    const int w = tid >> 5, l = tid & 31;
    const int pairbase = blockIdx.x * 8;
    const u64 neg1 = NEG1U;

    // ---- stage weights ----
    for (int i = tid; i < 300; i += 128) sW1[i] = gW1[i];
    for (int i = tid; i < 2400; i += 128) {
        int oc = i / 200, t = i - oc * 200;
        sW2[oc * 202 + t] = gW2[i];
    }

    // ---- load x (unpadded 16x16 per pair, packed into u64 halves) ----
    {
        const float* xsrc = gx + (size_t)pairbase * 512;
        int avail = (totalPairs - pairbase) * 2;
        int nval = (avail > 16 ? 16 : avail) * 256;
        for (int ii = tid; ii < 4096; ii += 128) {
            if (ii < nval) {
                int sl = ii >> 8, pix = ii & 255;
                ((float*)(xsU + (sl >> 1) * 257 + pix))[sl & 1] = xsrc[ii];
            }
        }
    }
    __syncthreads();

    // ---- conv1: 1 -> 12 ch, 5x5 s2, pad -1 -> 8x8, +bias, relu ----
    if (l < 24) {
        int idx = w * 24 + l;
        int p = idx / 12, c = idx - 12 * p;
        const u64* xp = xsU + p * 257;
        u64 wp[25];
#pragma unroll
        for (int i = 0; i < 25; i++) wp[i] = bcast(sW1[c * 25 + i]);
        // per-ky row sums (for fully-pad rows)
        u64 rs0 = add2(add2(add2(wp[0], wp[1]), add2(wp[2], wp[3])), wp[4]);
        u64 rs1 = add2(add2(add2(wp[5], wp[6]), add2(wp[7], wp[8])), wp[9]);
        u64 rs4 = add2(add2(add2(wp[20], wp[21]), add2(wp[22], wp[23])), wp[24]);
        const float* bias = gB1 + (c << 6);
        u64* a1c = a1U + (p * 12 + c) * 65;

        // y = 0: rows -2,-1 fully pad (-rs0-rs1), rows 0,1,2 real
        {
            u64 acc[8];
            u64 padc = add2(rs0, rs1);
#pragma unroll
            for (int xo = 0; xo < 8; xo++)
                acc[xo] = fma2(padc, neg1, bcast(bias[xo]));
            c1_row(xp +  0, wp + 10, acc, neg1);
            c1_row(xp + 16, wp + 15, acc, neg1);
            c1_row(xp + 32, wp + 20, acc, neg1);
#pragma unroll
            for (int xo = 0; xo < 8; xo++) a1c[xo] = relu2(acc[xo]);
        }
        // y = 1..6: all rows valid
#pragma unroll 1
        for (int y = 1; y < 7; y++) {
            u64 acc[8];
#pragma unroll
            for (int xo = 0; xo < 8; xo++) acc[xo] = bcast(bias[y * 8 + xo]);
#pragma unroll
            for (int ky = 0; ky < 5; ky++)
                c1_row(xp + (2 * y + ky - 2) * 16, wp + 5 * ky, acc, neg1);
#pragma unroll
            for (int xo = 0; xo < 8; xo++) a1c[y * 8 + xo] = relu2(acc[xo]);
        }
        // y = 7: rows 12..15 real (ky 0..3), row 16 fully pad (-rs4)
        {
            u64 acc[8];
#pragma unroll
            for (int xo = 0; xo < 8; xo++)
                acc[xo] = fma2(rs4, neg1, bcast(bias[56 + xo]));
            c1_row(xp + 12 * 16, wp +  0, acc, neg1);
            c1_row(xp + 13 * 16, wp +  5, acc, neg1);
            c1_row(xp + 14 * 16, wp + 10, acc, neg1);
            c1_row(xp + 15 * 16, wp + 15, acc, neg1);
#pragma unroll
            for (int xo = 0; xo < 8; xo++) a1c[56 + xo] = relu2(acc[xo]);
        }
    }
    __syncthreads();

    // ---- conv2: grouped 8-in-ch, 5x5 s2 on padded(-1) 12x12 -> 4x4 ----
    if (l < 24) {
        int idx = w * 24 + l;
        int p = idx / 12, oc = idx - 12 * p;
        int g = oc >> 2;
        u64 acc[16];
        const float* b2 = gB2 + oc * 16;
#pragma unroll
        for (int i = 0; i < 16; i++) acc[i] = bcast(b2[i]);
        const float* w2 = sW2 + oc * 202;
#pragma unroll 1
        for (int ic8 = 0; ic8 < 8; ic8++) {
            int cin = (g == 0) ? ic8
                    : (g == 1) ? (ic8 + 4)
                    : ((ic8 < 4) ? ic8 : ic8 + 4);
            u64 wv[25];
#pragma unroll
            for (int i = 0; i < 25; i++) wv[i] = bcast(w2[ic8 * 25 + i]);
            // fully-pad rows: iy=-2 (oy0,ky0), iy=-1 (oy0,ky1), iy=8 (oy3,ky4)
            u64 r01 = add2(add2(add2(add2(wv[0], wv[1]), add2(wv[2], wv[3])),
                                add2(add2(wv[4], wv[5]), add2(wv[6], wv[7]))),
                           add2(wv[8], wv[9]));
            u64 r4 = add2(add2(add2(wv[20], wv[21]), add2(wv[22], wv[23])), wv[24]);
#pragma unroll
            for (int ox = 0; ox < 4; ox++) {
                acc[ox]      = fma2(r01, neg1, acc[ox]);
                acc[12 + ox] = fma2(r4,  neg1, acc[12 + ox]);
            }
            const u64* plane = a1U + (p * 12 + cin) * 65;
#pragma unroll
            for (int iy = 0; iy < 8; iy++) {
                u64 rw[8];
#pragma unroll
                for (int i = 0; i < 8; i++) rw[i] = plane[iy * 8 + i];
#pragma unroll
                for (int oy = 0; oy < 4; oy++) {
                    int ky = iy + 2 - 2 * oy;
                    if (ky >= 0 && ky < 5) {
#pragma unroll
                        for (int kx = 0; kx < 5; kx++) {
                            u64 wvv = wv[ky * 5 + kx];
#pragma unroll
                            for (int ox = 0; ox < 4; ox++) {
                                int ix = 2 * ox + kx - 2;
                                u64 v = (ix >= 0 && ix < 8) ? rw[ix] : neg1;
                                acc[oy * 4 + ox] = fma2(v, wvv, acc[oy * 4 + ox]);
                            }
                        }
                    }
                }
            }
        }
        u64* a2p = a2U + p * 205 + oc * 17;
#pragma unroll
        for (int i = 0; i < 16; i++) a2p[i] = relu2(acc[i]);
    }
    __syncthreads();

    // ---- FC: warp w handles pairs 2w, 2w+1; lane = output neuron ----
    {
        int jl = l < 30 ? l : 29;
        u64 bj = bcast(gB3[jl]);
        const float* w3 = gW3 + jl;
#pragma unroll 1
        for (int pp = 0; pp < 2; pp++) {
            int p = w * 2 + pp;
            const u64* ap = a2U + p * 205;
            u64 a0 = bj, a1 = 0ull, a2 = 0ull, a3 = 0ull;
#pragma unroll 2
            for (int k = 0; k < 192; k += 4) {
                int off = k + (k >> 4);     // channel-stride-17 layout
                u64 x0 = ap[off], x1 = ap[off + 1];
                u64 x2 = ap[off + 2], x3 = ap[off + 3];
                a0 = fma2(x0, bcast(__ldg(w3 + (k    ) * 30)), a0);
                a1 = fma2(x1, bcast(__ldg(w3 + (k + 1) * 30)), a1);
                a2 = fma2(x2, bcast(__ldg(w3 + (k + 2) * 30)), a2);
                a3 = fma2(x3, bcast(__ldg(w3 + (k + 3) * 30)), a3);
            }
            u64 acc = relu2(add2(add2(a0, a1), add2(a2, a3)));
            if (l < 30) hsU[p * 30 + l] = acc;
            __syncwarp();
            if (l < 10) {
                u64 o = bcast(gBo[l]);
#pragma unroll
                for (int k = 0; k < 30; k++)
                    o = fma2(hsU[p * 30 + k], bcast(__ldg(gWo + k * 10 + l)), o);
                int gp = pairbase + p;
                if (gp < totalPairs) {
                    float2 f = unpack2(o);
                    gout[(size_t)(2 * gp) * 10 + l]     = f.x;
                    gout[(size_t)(2 * gp + 1) * 10 + l] = f.y;
                }
            }
            __syncwarp();
        }
    }
}

extern "C" void kernel_launch(void* const* d_in, const int* in_sizes, int n_in,
                              void* d_out, int out_size)
{
    const float* x  = (const float*)d_in[0];
    const float* w1 = (const float*)d_in[1];
    const float* b1 = (const float*)d_in[2];
    const float* w2 = (const float*)d_in[3];
    const float* b2 = (const float*)d_in[4];
    const float* w3 = (const float*)d_in[5];
    const float* b3 = (const float*)d_in[6];
    const float* wo = (const float*)d_in[7];
    const float* bo = (const float*)d_in[8];
    float* out = (float*)d_out;

    int Bn = in_sizes[0] / 256;
    int pairs = Bn / 2;
    int blocks = (pairs + 7) / 8;

    cudaFuncSetAttribute(modnet_kernel,
                         cudaFuncAttributeMaxDynamicSharedMemorySize, SMEM_BYTES);
    modnet_kernel<<<blocks, 128, SMEM_BYTES>>>(x, w1, b1, w2, b2, w3, b3,
                                               wo, bo, out, pairs);
}